// round 2
// baseline (speedup 1.0000x reference)
#include <cuda_runtime.h>

// AllZeroDigitalFilter via packed fma.rn.f32x2 (SASS FFMA2).
// out[b, n*P+p] = sum_k x[b, n*P+p-k] * (h0[b,n,k] + (p/P)*(h[b,n+1,k]-h[b,n,k]))
// B=8, N=800, P=80, taps=256. Two convolutions (h0 and d=h1-h0), blended at the end.

#define TAPS 256
#define MM   255
#define PP   80
#define SEG  8                    // segments per block
#define OUTB (SEG * PP)           // 640 outputs per block
#define RR   4                    // outputs per thread
#define NTHREADS (OUTB / RR)      // 160 threads (5 warps)
#define NB 800
#define BB 8
#define TT (NB * PP)              // 64000
#define QSTRIDE TAPS              // one float4 quad per tap per segment

typedef unsigned long long u64;

__device__ __forceinline__ u64 pack2(float lo, float hi) {
    u64 r; asm("mov.b64 %0, {%1,%2};" : "=l"(r) : "f"(lo), "f"(hi)); return r;
}
__device__ __forceinline__ void unpack2(u64 v, float& lo, float& hi) {
    asm("mov.b64 {%0,%1}, %2;" : "=f"(lo), "=f"(hi) : "l"(v));
}
__device__ __forceinline__ u64 ffma2(u64 a, u64 b, u64 c) {
    u64 d; asm("fma.rn.f32x2 %0, %1, %2, %3;" : "=l"(d) : "l"(a), "l"(b), "l"(c)); return d;
}

union F4U {
    float4 f4;
    struct { u64 lo, hi; } u;
};

__global__ __launch_bounds__(NTHREADS)
void azdf_kernel(const float* __restrict__ x,
                 const float* __restrict__ h,
                 float* __restrict__ out)
{
    // per-tap coeff quad {h0, h0, d, d} (lane-duplicated for f32x2)
    __shared__ float4 sq[SEG * QSTRIDE];       // 32 KB
    __shared__ float  sx[8 + TAPS + OUTB];     // 3.6 KB (8-float front pad)

    const int tid = threadIdx.x;
    const int b   = blockIdx.y;
    const int n0  = blockIdx.x * SEG;

    // ---- stage filters: one quad per (segment, tap)
    {
        const float* hb = h + (size_t)b * NB * TAPS;
        for (int idx = tid; idx < SEG * TAPS; idx += NTHREADS) {
            int s = idx >> 8;
            int k = idx & (TAPS - 1);
            int n  = n0 + s;
            int nn = (n + 1 < NB) ? (n + 1) : (NB - 1);
            float a = hb[(size_t)n  * TAPS + k];
            float c = hb[(size_t)nn * TAPS + k];
            float d = c - a;
            sq[s * QSTRIDE + k] = make_float4(a, a, d, d);
        }
    }
    // ---- stage x window: global [n0*P - M, n0*P - M + 895], zero-pad OOB
    {
        const float* xb = x + (size_t)b * TT;
        const int gbase = n0 * PP - MM;
        for (int j = tid; j < TAPS + OUTB; j += NTHREADS) {
            int g = gbase + j;
            sx[8 + j] = (g >= 0 && g < TT) ? xb[g] : 0.0f;
        }
        if (tid < 8) sx[tid] = 0.0f;
    }
    __syncthreads();

    const int pout = tid * RR;
    const int s    = tid / (PP / RR);          // tid/20
    const float4* cq = sq + s * QSTRIDE;
    const float* sxo = sx + 8;

    // Window invariant: W[i] = sxo[pout + 252 - 4*kk + i], i = 0..7
    // P0={W0,W1} P1={W2,W3} P2={W4,W5} P3={W6,W7}  (even-phase pairs)
    // Q0={W1,W2} Q1={W3,W4} Q2={W5,W6}             (odd-phase pairs)
    u64 P0, P1, P2, P3, Q0, Q1, Q2;
    float w0s;
    {
        F4U a, c;
        a.f4 = *(const float4*)(sxo + pout + 252);
        c.f4 = *(const float4*)(sxo + pout + 256);
        P0 = a.u.lo; P1 = a.u.hi; P2 = c.u.lo; P3 = c.u.hi;
        Q0 = pack2(a.f4.y, a.f4.z);
        Q1 = pack2(a.f4.w, c.f4.x);
        Q2 = pack2(c.f4.y, c.f4.z);
        w0s = a.f4.x;
    }

    // accumulators: A = conv with h0, B = conv with d; lanes = output pairs (0,1) and (2,3)
    u64 A0 = 0ull, A1 = 0ull, B0 = 0ull, B1 = 0ull;

    #pragma unroll 4
    for (int kk = 0; kk < TAPS / 4; kk++) {
        const float4* cqk = cq + kk * 4;
        // tap u: xp01 = {W[3-u],W[4-u]}, xp23 = {W[5-u],W[6-u]}
        {   // u = 0
            F4U cu; cu.f4 = cqk[0];
            A0 = ffma2(Q1, cu.u.lo, A0); A1 = ffma2(Q2, cu.u.lo, A1);
            B0 = ffma2(Q1, cu.u.hi, B0); B1 = ffma2(Q2, cu.u.hi, B1);
        }
        {   // u = 1
            F4U cu; cu.f4 = cqk[1];
            A0 = ffma2(P1, cu.u.lo, A0); A1 = ffma2(P2, cu.u.lo, A1);
            B0 = ffma2(P1, cu.u.hi, B0); B1 = ffma2(P2, cu.u.hi, B1);
        }
        {   // u = 2
            F4U cu; cu.f4 = cqk[2];
            A0 = ffma2(Q0, cu.u.lo, A0); A1 = ffma2(Q1, cu.u.lo, A1);
            B0 = ffma2(Q0, cu.u.hi, B0); B1 = ffma2(Q1, cu.u.hi, B1);
        }
        {   // u = 3
            F4U cu; cu.f4 = cqk[3];
            A0 = ffma2(P0, cu.u.lo, A0); A1 = ffma2(P1, cu.u.lo, A1);
            B0 = ffma2(P0, cu.u.hi, B0); B1 = ffma2(P1, cu.u.hi, B1);
        }
        // slide window down by 4 (final iteration's load is dead; lands in front pad)
        F4U nw; nw.f4 = *(const float4*)(sxo + pout + 248 - 4 * kk);
        u64 nQ0 = pack2(nw.f4.y, nw.f4.z);
        u64 nQ1 = pack2(nw.f4.w, w0s);
        P2 = P0; P3 = P1; Q2 = Q0;
        P0 = nw.u.lo; P1 = nw.u.hi;
        Q0 = nQ0; Q1 = nQ1;
        w0s = nw.f4.x;
    }

    float a00, a01, a02, a03, a10, a11, a12, a13;
    unpack2(A0, a00, a01); unpack2(A1, a02, a03);
    unpack2(B0, a10, a11); unpack2(B1, a12, a13);

    const float pb  = (float)(pout % PP);
    const float inv = 1.0f / (float)PP;
    float4 o;
    o.x = a00 + (pb + 0.0f) * inv * a10;
    o.y = a01 + (pb + 1.0f) * inv * a11;
    o.z = a02 + (pb + 2.0f) * inv * a12;
    o.w = a03 + (pb + 3.0f) * inv * a13;
    *(float4*)(out + (size_t)b * TT + n0 * PP + pout) = o;
}

extern "C" void kernel_launch(void* const* d_in, const int* in_sizes, int n_in,
                              void* d_out, int out_size)
{
    const float* x = (const float*)d_in[0];
    const float* h = (const float*)d_in[1];
    float* out = (float*)d_out;
    (void)in_sizes; (void)n_in; (void)out_size;

    dim3 grid(NB / SEG, BB);   // 100 x 8 = 800 blocks
    azdf_kernel<<<grid, NTHREADS>>>(x, h, out);
}

// round 3
// speedup vs baseline: 1.1954x; 1.1954x over previous
#include <cuda_runtime.h>

// AllZeroDigitalFilter via FFMA2 (fma.rn.f32x2), pairing the two convolutions
// {y0, y1} in the 64-bit lanes:
//   out[b, n*P+p] = y0 + (p/P)*y1,  y0 = x*h0,  y1 = x*(h1-h0)
// Coefficients staged as interleaved {h0[k], d[k]} pairs (one LDS.128 = 2 taps).
// x window kept as lane-duplicated pairs {w,w}. B=8, N=800, P=80, taps=256.

#define TAPS 256
#define MM   255
#define PP   80
#define SEG  8                    // segments per block
#define OUTB (SEG * PP)           // 640 outputs per block
#define RR   4                    // outputs per thread
#define NTHREADS (OUTB / RR)      // 160 threads (5 warps)
#define NB 800
#define BB 8
#define TT (NB * PP)              // 64000
#define CPSTRIDE (TAPS + 4)       // float2 units per segment (+4 pad)

typedef unsigned long long u64;

__device__ __forceinline__ u64 dup2(float v) {
    u64 r; asm("mov.b64 %0, {%1,%1};" : "=l"(r) : "f"(v)); return r;
}
__device__ __forceinline__ void unpack2(u64 v, float& lo, float& hi) {
    asm("mov.b64 {%0,%1}, %2;" : "=f"(lo), "=f"(hi) : "l"(v));
}
__device__ __forceinline__ u64 ffma2(u64 a, u64 b, u64 c) {
    u64 d; asm("fma.rn.f32x2 %0, %1, %2, %3;" : "=l"(d) : "l"(a), "l"(b), "l"(c)); return d;
}

union F4U {
    float4 f4;
    struct { u64 lo, hi; } u;   // lo = {f4.x, f4.y}, hi = {f4.z, f4.w}
};

__global__ __launch_bounds__(NTHREADS)
void azdf_kernel(const float* __restrict__ x,
                 const float* __restrict__ h,
                 float* __restrict__ out)
{
    __shared__ float2 scp[SEG * CPSTRIDE];     // interleaved {h0, d} per tap: ~16.6 KB
    __shared__ float  sx[8 + TAPS + OUTB];     // 8-float front pad + 896-value x window

    const int tid = threadIdx.x;
    const int b   = blockIdx.y;
    const int n0  = blockIdx.x * SEG;

    // ---- stage filters as {h0, d} pairs
    {
        const float* hb = h + (size_t)b * NB * TAPS;
        for (int idx = tid; idx < SEG * TAPS; idx += NTHREADS) {
            int s = idx >> 8;
            int k = idx & (TAPS - 1);
            int n  = n0 + s;
            int nn = (n + 1 < NB) ? (n + 1) : (NB - 1);
            float a = hb[(size_t)n  * TAPS + k];
            float c = hb[(size_t)nn * TAPS + k];
            scp[s * CPSTRIDE + k] = make_float2(a, c - a);
        }
    }
    // ---- stage x window: global [n0*P - M, n0*P - M + 895], zero-pad OOB
    {
        const float* xb = x + (size_t)b * TT;
        const int gbase = n0 * PP - MM;
        for (int j = tid; j < TAPS + OUTB; j += NTHREADS) {
            int g = gbase + j;
            sx[8 + j] = (g >= 0 && g < TT) ? xb[g] : 0.0f;
        }
        if (tid < 8) sx[tid] = 0.0f;
    }
    __syncthreads();

    const int pout = tid * RR;
    const int s    = tid / (PP / RR);          // tid/20
    const float2* cp = scp + s * CPSTRIDE;
    const float* sxo = sx + 8;

    // Window invariant: D[i] = {W,W} with W = sxo[pout + 252 - 4*kk + i], i = 0..7
    u64 D0, D1, D2, D3, D4, D5, D6, D7;
    {
        float4 a = *(const float4*)(sxo + pout + 252);
        float4 c = *(const float4*)(sxo + pout + 256);
        D0 = dup2(a.x); D1 = dup2(a.y); D2 = dup2(a.z); D3 = dup2(a.w);
        D4 = dup2(c.x); D5 = dup2(c.y); D6 = dup2(c.z); D7 = dup2(c.w);
    }

    // accumulators: Y_r = {y0_r, y1_r} for outputs r = 0..3
    u64 Y0 = 0ull, Y1 = 0ull, Y2 = 0ull, Y3 = 0ull;

    #pragma unroll 4
    for (int kk = 0; kk < TAPS / 4; kk++) {
        // 2 x LDS.128 = 4 taps of {h0,d} pairs
        F4U ca, cb;
        ca.f4 = *(const float4*)(cp + kk * 4);       // taps 4kk, 4kk+1
        cb.f4 = *(const float4*)(cp + kk * 4 + 2);   // taps 4kk+2, 4kk+3

        // tap u: output r uses D[3 - u + r]
        Y0 = ffma2(D3, ca.u.lo, Y0); Y1 = ffma2(D4, ca.u.lo, Y1);   // u=0
        Y2 = ffma2(D5, ca.u.lo, Y2); Y3 = ffma2(D6, ca.u.lo, Y3);
        Y0 = ffma2(D2, ca.u.hi, Y0); Y1 = ffma2(D3, ca.u.hi, Y1);   // u=1
        Y2 = ffma2(D4, ca.u.hi, Y2); Y3 = ffma2(D5, ca.u.hi, Y3);
        Y0 = ffma2(D1, cb.u.lo, Y0); Y1 = ffma2(D2, cb.u.lo, Y1);   // u=2
        Y2 = ffma2(D3, cb.u.lo, Y2); Y3 = ffma2(D4, cb.u.lo, Y3);
        Y0 = ffma2(D0, cb.u.hi, Y0); Y1 = ffma2(D1, cb.u.hi, Y1);   // u=3
        Y2 = ffma2(D2, cb.u.hi, Y2); Y3 = ffma2(D3, cb.u.hi, Y3);

        // slide window down by 4 (final iteration's load lands in the front pad)
        float4 nw = *(const float4*)(sxo + pout + 248 - 4 * kk);
        D4 = D0; D5 = D1; D6 = D2; D7 = D3;
        D0 = dup2(nw.x); D1 = dup2(nw.y); D2 = dup2(nw.z); D3 = dup2(nw.w);
    }
    (void)D7;

    float y00, y10, y01, y11, y02, y12, y03, y13;
    unpack2(Y0, y00, y10); unpack2(Y1, y01, y11);
    unpack2(Y2, y02, y12); unpack2(Y3, y03, y13);

    const float pb  = (float)(pout % PP);
    const float inv = 1.0f / (float)PP;
    float4 o;
    o.x = y00 + (pb + 0.0f) * inv * y10;
    o.y = y01 + (pb + 1.0f) * inv * y11;
    o.z = y02 + (pb + 2.0f) * inv * y12;
    o.w = y03 + (pb + 3.0f) * inv * y13;
    *(float4*)(out + (size_t)b * TT + n0 * PP + pout) = o;
}

extern "C" void kernel_launch(void* const* d_in, const int* in_sizes, int n_in,
                              void* d_out, int out_size)
{
    const float* x = (const float*)d_in[0];
    const float* h = (const float*)d_in[1];
    float* out = (float*)d_out;
    (void)in_sizes; (void)n_in; (void)out_size;

    dim3 grid(NB / SEG, BB);   // 100 x 8 = 800 blocks
    azdf_kernel<<<grid, NTHREADS>>>(x, h, out);
}

// round 4
// speedup vs baseline: 1.3050x; 1.0917x over previous
#include <cuda_runtime.h>

// AllZeroDigitalFilter, scalar FFMA (3-reg rt=2 is the structural rate; FFMA2 was
// a wash — 6 RF reads). This version targets issue efficiency:
//   - K-split x2: two 160-thread teams each do 128 of the 256 taps (10 warps/block)
//   - software-pipelined coefficient + x-window LDS (prefetch one iter ahead)
// out[b, n*P+p] = y0 + (p/P)*y1,  y0 = x*h0,  y1 = x*(h1-h0)

#define TAPS 256
#define HALF 128
#define MM   255
#define PP   80
#define SEG  8
#define OUTB (SEG * PP)            // 640 outputs per block
#define RR   4
#define TEAM (OUTB / RR)           // 160 threads per team
#define NTHREADS (2 * TEAM)        // 320 threads
#define FSTRIDE (2 * TAPS + 8)     // h0[256] | d[256] | pad8
#define NB 800
#define BB 8
#define TT (NB * PP)

__global__ __launch_bounds__(NTHREADS)
void azdf_kernel(const float* __restrict__ x,
                 const float* __restrict__ h,
                 float* __restrict__ out)
{
    __shared__ float sf[SEG * FSTRIDE];        // 16.6 KB filters
    __shared__ float sx[8 + TAPS + OUTB];      // 3.6 KB x window (8-float front pad)
    __shared__ float spart[TEAM * 8];          // 5.1 KB team-1 partials

    const int tid = threadIdx.x;
    const int b   = blockIdx.y;
    const int n0  = blockIdx.x * SEG;

    // ---- stage filters: h0 and d = h1-h0 per segment
    {
        const float4* hb = (const float4*)(h + (size_t)b * NB * TAPS);
        for (int idx = tid; idx < SEG * (TAPS / 4); idx += NTHREADS) {
            int s  = idx >> 6;
            int k4 = idx & 63;
            int n  = n0 + s;
            int nn = (n + 1 < NB) ? (n + 1) : (NB - 1);
            float4 a = hb[n  * (TAPS / 4) + k4];
            float4 c = hb[nn * (TAPS / 4) + k4];
            float* f0 = sf + s * FSTRIDE;
            float* f1 = f0 + TAPS;
            f0[k4 * 4 + 0] = a.x; f0[k4 * 4 + 1] = a.y;
            f0[k4 * 4 + 2] = a.z; f0[k4 * 4 + 3] = a.w;
            f1[k4 * 4 + 0] = c.x - a.x; f1[k4 * 4 + 1] = c.y - a.y;
            f1[k4 * 4 + 2] = c.z - a.z; f1[k4 * 4 + 3] = c.w - a.w;
        }
    }
    // ---- stage x window: global [n0*P - M, n0*P - M + 895], zero-pad OOB
    {
        const float* xb = x + (size_t)b * TT;
        const int gbase = n0 * PP - MM;
        for (int j = tid; j < TAPS + OUTB; j += NTHREADS) {
            int g = gbase + j;
            sx[8 + j] = (g >= 0 && g < TT) ? xb[g] : 0.0f;
        }
        if (tid < 8) sx[tid] = 0.0f;
    }
    __syncthreads();

    const int lane = (tid < TEAM) ? tid : (tid - TEAM);   // 0..159 within team
    const int team = (tid < TEAM) ? 0 : 1;
    const int koff = team * HALF;                          // tap offset for this team
    const int pout = lane * RR;
    const int s    = lane / (PP / RR);                     // lane/20
    const float* f0  = sf + s * FSTRIDE + koff;
    const float* f1  = f0 + TAPS;
    const float* sxo = sx + 8;
    const float* wbase = sxo + pout - koff;                // window base

    float a00 = 0.f, a01 = 0.f, a02 = 0.f, a03 = 0.f;      // conv h0
    float a10 = 0.f, a11 = 0.f, a12 = 0.f, a13 = 0.f;      // conv d

    // Window invariant at iter kk (0..31): W[i] = wbase[252 - 4*kk + i]
    float W0, W1, W2, W3, W4, W5, W6, W7;
    {
        float4 w0 = *(const float4*)(wbase + 252);
        float4 w1 = *(const float4*)(wbase + 256);
        W0 = w0.x; W1 = w0.y; W2 = w0.z; W3 = w0.w;
        W4 = w1.x; W5 = w1.y; W6 = w1.z; W7 = w1.w;
    }
    // current coefficients (taps 4kk..4kk+3)
    float4 c0 = *(const float4*)(f0);
    float4 c1 = *(const float4*)(f1);

    #pragma unroll 4
    for (int kk = 0; kk < HALF / 4; kk++) {
        // ---- prefetch next iteration's operands (over-reads land in pads)
        float4 nw  = *(const float4*)(wbase + 248 - 4 * kk);
        float4 nc0 = *(const float4*)(f0 + 4 * kk + 4);
        float4 nc1 = *(const float4*)(f1 + 4 * kk + 4);

        // ---- 32 FFMA on current window/coeffs
        a00 += W3 * c0.x; a01 += W4 * c0.x; a02 += W5 * c0.x; a03 += W6 * c0.x;
        a10 += W3 * c1.x; a11 += W4 * c1.x; a12 += W5 * c1.x; a13 += W6 * c1.x;
        a00 += W2 * c0.y; a01 += W3 * c0.y; a02 += W4 * c0.y; a03 += W5 * c0.y;
        a10 += W2 * c1.y; a11 += W3 * c1.y; a12 += W4 * c1.y; a13 += W5 * c1.y;
        a00 += W1 * c0.z; a01 += W2 * c0.z; a02 += W3 * c0.z; a03 += W4 * c0.z;
        a10 += W1 * c1.z; a11 += W2 * c1.z; a12 += W3 * c1.z; a13 += W4 * c1.z;
        a00 += W0 * c0.w; a01 += W1 * c0.w; a02 += W2 * c0.w; a03 += W3 * c0.w;
        a10 += W0 * c1.w; a11 += W1 * c1.w; a12 += W2 * c1.w; a13 += W3 * c1.w;

        // ---- apply prefetched slide + coeff swap
        W4 = W0; W5 = W1; W6 = W2; W7 = W3;
        W0 = nw.x; W1 = nw.y; W2 = nw.z; W3 = nw.w;
        c0 = nc0; c1 = nc1;
    }
    (void)W7;

    if (team == 1) {
        float* sp = spart + lane * 8;
        sp[0] = a00; sp[1] = a01; sp[2] = a02; sp[3] = a03;
        sp[4] = a10; sp[5] = a11; sp[6] = a12; sp[7] = a13;
    }
    __syncthreads();
    if (team == 0) {
        const float* sp = spart + lane * 8;
        a00 += sp[0]; a01 += sp[1]; a02 += sp[2]; a03 += sp[3];
        a10 += sp[4]; a11 += sp[5]; a12 += sp[6]; a13 += sp[7];

        const float pb  = (float)(pout % PP);
        const float inv = 1.0f / (float)PP;
        float4 o;
        o.x = a00 + (pb + 0.0f) * inv * a10;
        o.y = a01 + (pb + 1.0f) * inv * a11;
        o.z = a02 + (pb + 2.0f) * inv * a12;
        o.w = a03 + (pb + 3.0f) * inv * a13;
        *(float4*)(out + (size_t)b * TT + n0 * PP + pout) = o;
    }
}

extern "C" void kernel_launch(void* const* d_in, const int* in_sizes, int n_in,
                              void* d_out, int out_size)
{
    const float* x = (const float*)d_in[0];
    const float* h = (const float*)d_in[1];
    float* out = (float*)d_out;
    (void)in_sizes; (void)n_in; (void)out_size;

    dim3 grid(NB / SEG, BB);   // 100 x 8 = 800 blocks
    azdf_kernel<<<grid, NTHREADS>>>(x, h, out);
}